// round 11
// baseline (speedup 1.0000x reference)
#include <cuda_runtime.h>
#include <cuda_bf16.h>
#include <cstdint>

// ---------------------------------------------------------------------------
// Static scratch (no allocation allowed)
// ---------------------------------------------------------------------------
__device__ float g_bufA[16777216];
__device__ float g_bufB[4194304];
__device__ float g_Wp[279936];      // [k1lin 27][k2lin 27][ci 128][co 3]
__device__ float g_WpT[279936];     // [k1lin 27][k2lin 27][co 3][ci 128]
__device__ float g_Weff[110592];    // [pz 8][dxlin 27][co 3][ci 128]
__device__ float g_bconv[81];       // [k2lin 27][co 3]
__device__ float g_btot[3];
__device__ __nv_bfloat16 g_xhi[4194304];
__device__ __nv_bfloat16 g_xlo[4194304];
__device__ __nv_bfloat16 g_whi[442368];    // L4 weights (w10)
__device__ __nv_bfloat16 g_wlo[442368];
__device__ __nv_bfloat16 g_whiB[442368];   // L3 weights (w1)
__device__ __nv_bfloat16 g_wloB[442368];

typedef unsigned long long ull;

// ---------------------------------------------------------------------------
// f32x2 packed helpers
// ---------------------------------------------------------------------------
__device__ __forceinline__ ull pack2(float x, float y){
  ull r; asm("mov.b64 %0, {%1, %2};" : "=l"(r) : "f"(x), "f"(y)); return r;
}
__device__ __forceinline__ void unpack2(ull v, float& x, float& y){
  asm("mov.b64 {%0, %1}, %2;" : "=f"(x), "=f"(y) : "l"(v));
}
__device__ __forceinline__ void ffma2(ull& acc, ull a, ull b){
  asm("fma.rn.f32x2 %0, %1, %2, %0;" : "+l"(acc) : "l"(a), "l"(b));
}

// ---------------------------------------------------------------------------
// mma.sync / ldmatrix / cp.async helpers (baseline PTX, legal on sm_103)
// ---------------------------------------------------------------------------
__device__ __forceinline__ void ldsm4(uint32_t* r, const void* p){
  uint32_t a = (uint32_t)__cvta_generic_to_shared(p);
  asm volatile("ldmatrix.sync.aligned.m8n8.x4.shared.b16 {%0,%1,%2,%3}, [%4];"
    : "=r"(r[0]), "=r"(r[1]), "=r"(r[2]), "=r"(r[3]) : "r"(a));
}
__device__ __forceinline__ void ldsm4t(uint32_t* r, const void* p){
  uint32_t a = (uint32_t)__cvta_generic_to_shared(p);
  asm volatile("ldmatrix.sync.aligned.m8n8.x4.trans.shared.b16 {%0,%1,%2,%3}, [%4];"
    : "=r"(r[0]), "=r"(r[1]), "=r"(r[2]), "=r"(r[3]) : "r"(a));
}
__device__ __forceinline__ void mma_bf16(float* c, const uint32_t* a,
                                         uint32_t b0, uint32_t b1){
  asm volatile("mma.sync.aligned.m16n8k16.row.col.f32.bf16.bf16.f32 "
    "{%0,%1,%2,%3}, {%4,%5,%6,%7}, {%8,%9}, {%0,%1,%2,%3};"
    : "+f"(c[0]), "+f"(c[1]), "+f"(c[2]), "+f"(c[3])
    : "r"(a[0]), "r"(a[1]), "r"(a[2]), "r"(a[3]), "r"(b0), "r"(b1));
}
__device__ __forceinline__ void cpasync16(void* dst, const void* src, bool pred){
  uint32_t d = (uint32_t)__cvta_generic_to_shared(dst);
  int sz = pred ? 16 : 0;
  asm volatile("cp.async.cg.shared.global [%0], [%1], 16, %2;"
               :: "r"(d), "l"(src), "r"(sz));
}
#define CP_COMMIT() asm volatile("cp.async.commit_group;")
#define CP_WAIT1()  asm volatile("cp.async.wait_group 1;")
#define CP_WAIT0()  asm volatile("cp.async.wait_group 0;")

// ---------------------------------------------------------------------------
// ROUND-1 PROVEN KERNEL (verbatim): generic transposed-conv implicit GEMM.
// ---------------------------------------------------------------------------
template<int BM, int TM>
__global__ __launch_bounds__(256) void deconv_gemm(
    const float* __restrict__ x, const float* __restrict__ w,
    const float* __restrict__ bias, float* __restrict__ out,
    int inD, int inH, int inW, int Cin,
    int outD, int outH, int outW, int Cout,
    int stride, int relu)
{
  constexpr int BN = 64;
  constexpr int BK = 16;
  constexpr int NP = TM / 2;

  __shared__ float As[BK][BM];
  __shared__ float Bs[BK][BN];
  __shared__ int   offs[BM];

  const int tid = threadIdx.x;
  const int pz = blockIdx.z;
  const int pd = (pz >> 2) & 1, ph = (pz >> 1) & 1, pw = pz & 1;
  const int rH = outH / stride, rW = outW / stride;
  const int nb = blockIdx.y * BN;
  const int vbase = blockIdx.x * BM;

  int md = 0, mh = 0, mw = 0;
  if (tid < BM) {
    int rv = vbase + tid;
    mw = rv % rW; int t = rv / rW; mh = t % rH; md = t / rH;
  }

  int nkd, kdL[3], ddL[3];
  int nkh, khL[3], dhL[3];
  int nkw, kwL[3], dwL[3];
  auto mk = [&](int p, int& n, int* kL, int* dL){
    if (stride == 1){ n = 3; kL[0]=0; kL[1]=1; kL[2]=2; dL[0]=-1; dL[1]=0; dL[2]=1; }
    else if (p == 0){ n = 2; kL[0]=0; kL[1]=2; dL[0]=-1; dL[1]=0; }
    else            { n = 1; kL[0]=1; dL[0]=0; }
  };
  mk(pd, nkd, kdL, ddL);
  mk(ph, nkh, khL, dhL);
  mk(pw, nkw, kwL, dwL);

  const int mg = tid >> 4, ng = tid & 15;
  const int m0 = mg * TM, n0 = ng * 4;

  ull acc[NP][4];
  #pragma unroll
  for (int i = 0; i < NP; i++)
    #pragma unroll
    for (int j = 0; j < 4; j++) acc[i][j] = 0ull;

  for (int ia = 0; ia < nkd; ia++)
  for (int ib = 0; ib < nkh; ib++)
  for (int ic = 0; ic < nkw; ic++){
    const int tap = (kdL[ia]*3 + khL[ib])*3 + kwL[ic];
    const float* wt = w + (size_t)tap * Cin * Cout + nb;

    __syncthreads();
    if (tid < BM){
      int id = md + ddL[ia];
      int ih = mh + dhL[ib];
      int iw = mw + dwL[ic];
      bool v = (unsigned)id < (unsigned)inD &&
               (unsigned)ih < (unsigned)inH &&
               (unsigned)iw < (unsigned)inW;
      offs[tid] = v ? ((id*inH + ih)*inW + iw) * Cin : -1;
    }

    for (int c0 = 0; c0 < Cin; c0 += BK){
      __syncthreads();
      for (int idx = tid; idx < BM*4; idx += 256){
        int v = idx >> 2, c4 = (idx & 3) * 4;
        int o = offs[v];
        float4 val = make_float4(0.f, 0.f, 0.f, 0.f);
        if (o >= 0) val = *(const float4*)(x + o + c0 + c4);
        As[c4+0][v] = val.x; As[c4+1][v] = val.y;
        As[c4+2][v] = val.z; As[c4+3][v] = val.w;
      }
      {
        int r = tid >> 4, col = (tid & 15) * 4;
        float4 bv = *(const float4*)(wt + (size_t)(c0 + r) * Cout + col);
        *(float4*)&Bs[r][col] = bv;
      }
      __syncthreads();
      #pragma unroll
      for (int kk = 0; kk < BK; kk++){
        const ull* a64 = (const ull*)&As[kk][m0];
        float4 bv = *(const float4*)&Bs[kk][n0];
        ull bp0 = pack2(bv.x, bv.x);
        ull bp1 = pack2(bv.y, bv.y);
        ull bp2 = pack2(bv.z, bv.z);
        ull bp3 = pack2(bv.w, bv.w);
        #pragma unroll
        for (int i = 0; i < NP; i++){
          ull av = a64[i];
          ffma2(acc[i][0], av, bp0);
          ffma2(acc[i][1], av, bp1);
          ffma2(acc[i][2], av, bp2);
          ffma2(acc[i][3], av, bp3);
        }
      }
    }
  }

  float4 b4 = *(const float4*)&bias[nb + n0];
  #pragma unroll
  for (int i = 0; i < NP; i++){
    float r0[4], r1[4];
    #pragma unroll
    for (int j = 0; j < 4; j++) unpack2(acc[i][j], r0[j], r1[j]);
    #pragma unroll
    for (int h = 0; h < 2; h++){
      float* rr = h ? r1 : r0;
      int rv = vbase + m0 + 2*i + h;
      int vw = rv % rW; int t = rv / rW; int vh = t % rH; int vd = t / rH;
      int od = vd*stride + pd, oh = vh*stride + ph, ow = vw*stride + pw;
      size_t oo = (size_t)((od*outH + oh)*outW + ow) * Cout + nb + n0;
      float4 res;
      res.x = rr[0] + b4.x; res.y = rr[1] + b4.y;
      res.z = rr[2] + b4.z; res.w = rr[3] + b4.w;
      if (relu){
        res.x = fmaxf(res.x, 0.f); res.y = fmaxf(res.y, 0.f);
        res.z = fmaxf(res.z, 0.f); res.w = fmaxf(res.w, 0.f);
      }
      *(float4*)&out[oo] = res;
    }
  }
}

// ---------------------------------------------------------------------------
// bf16 hi/lo split pre-passes (R9-proven, verbatim)
// ---------------------------------------------------------------------------
__global__ __launch_bounds__(256) void split_x_kernel(
    const float* __restrict__ x, __nv_bfloat16* __restrict__ hi,
    __nv_bfloat16* __restrict__ lo, int n4)
{
  int i = blockIdx.x * 256 + threadIdx.x;
  if (i >= n4) return;
  float4 v = ((const float4*)x)[i];
  __nv_bfloat16 h0 = __float2bfloat16_rn(v.x);
  __nv_bfloat16 h1 = __float2bfloat16_rn(v.y);
  __nv_bfloat16 h2 = __float2bfloat16_rn(v.z);
  __nv_bfloat16 h3 = __float2bfloat16_rn(v.w);
  __nv_bfloat16 l0 = __float2bfloat16_rn(v.x - __bfloat162float(h0));
  __nv_bfloat16 l1 = __float2bfloat16_rn(v.y - __bfloat162float(h1));
  __nv_bfloat16 l2 = __float2bfloat16_rn(v.z - __bfloat162float(h2));
  __nv_bfloat16 l3 = __float2bfloat16_rn(v.w - __bfloat162float(h3));
  ushort4 hv = make_ushort4(*(unsigned short*)&h0, *(unsigned short*)&h1,
                            *(unsigned short*)&h2, *(unsigned short*)&h3);
  ushort4 lv = make_ushort4(*(unsigned short*)&l0, *(unsigned short*)&l1,
                            *(unsigned short*)&l2, *(unsigned short*)&l3);
  ((ushort4*)hi)[i] = hv;
  ((ushort4*)lo)[i] = lv;
}

__global__ __launch_bounds__(256) void split_w_kernel(
    const float* __restrict__ w, __nv_bfloat16* __restrict__ hi,
    __nv_bfloat16* __restrict__ lo)
{
  int i = blockIdx.x * 256 + threadIdx.x;
  if (i >= 27*128*128) return;
  float v = w[i];
  __nv_bfloat16 h = __float2bfloat16_rn(v);
  hi[i] = h;
  lo[i] = __float2bfloat16_rn(v - __bfloat162float(h));
}

// ---------------------------------------------------------------------------
// NEW (round 11): L4 on HMMA with cp.async 2-stage pipeline.
// Compute core (ldsm/mma/epilogue) is the R9-proven mma_s1r core verbatim;
// the fills become cp.async (zero-fill for invalid gather rows), with all
// 27 taps' offs precomputed once into SMEM.
// Dynamic SMEM: 2 stages x (Ahi|Alo|Bhi|Blo) + offs[27][128] = 89600 B.
// ---------------------------------------------------------------------------
__global__ __launch_bounds__(256, 2) void mma_s1r_pipe(
    const __nv_bfloat16* __restrict__ xhi, const __nv_bfloat16* __restrict__ xlo,
    const __nv_bfloat16* __restrict__ whi, const __nv_bfloat16* __restrict__ wlo,
    const float* __restrict__ bias, float* __restrict__ out)
{
  constexpr int AP = 40, BP = 136;
  constexpr int ASZ = 128*AP;          // 5120 ushort
  constexpr int BSZ = 32*BP;           // 4352 ushort
  constexpr int STG = 2*ASZ + 2*BSZ;   // 18944 ushort = 37888 B per stage
  constexpr int NIT = 27*4;            // 108 iterations

  extern __shared__ __align__(16) unsigned short dsm[];
  int* offsAll = (int*)(dsm + 2*STG);  // [27][128]

  const int tid  = threadIdx.x;
  const int lane = tid & 31;
  const int wid  = tid >> 5;
  const int warp_m = wid >> 2;
  const int warp_n = wid & 3;
  const int vbase = blockIdx.x * 128;

  // precompute gather offsets for all taps
  for (int s = tid; s < 27*128; s += 256){
    int tap = s >> 7, row = s & 127;
    int kw = tap % 3, kh = (tap/3)%3, kd = tap/9;
    int rv = vbase + row;
    int mw = rv & 31, mh = (rv>>5)&31, md = rv>>10;
    int id = md + kd - 1, ih = mh + kh - 1, iw = mw + kw - 1;
    bool v = (unsigned)id < 32u && (unsigned)ih < 32u && (unsigned)iw < 32u;
    offsAll[s] = v ? ((id*32 + ih)*32 + iw) * 128 : -1;
  }
  __syncthreads();

  const int a_row_in = lane & 15;
  const int a_colb   = (lane >> 4) << 3;
  const int b_krow   = lane & 15;
  const int b_coln   = (lane >> 4) << 3;

  float acc[4][4][4];
  #pragma unroll
  for (int mi = 0; mi < 4; mi++)
    #pragma unroll
    for (int ni = 0; ni < 4; ni++)
      #pragma unroll
      for (int q = 0; q < 4; q++) acc[mi][ni][q] = 0.f;

  auto fill = [&](int st, int it){
    int tap = it >> 2, c0 = (it & 3) * 32;
    unsigned short* Ah = dsm + st*STG;
    unsigned short* Al = Ah + ASZ;
    unsigned short* Bh = Ah + 2*ASZ;
    unsigned short* Bl = Bh + BSZ;
    #pragma unroll
    for (int rep = 0; rep < 2; rep++){
      int idx = rep*256 + tid;
      int row = idx >> 2, cg = idx & 3;
      int o = offsAll[tap*128 + row];
      bool p = o >= 0;
      int ob = (p ? o : 0) + c0 + cg*8;
      cpasync16(&Ah[row*AP + cg*8], xhi + ob, p);
      cpasync16(&Al[row*AP + cg*8], xlo + ob, p);
    }
    #pragma unroll
    for (int rep = 0; rep < 2; rep++){
      int idx = rep*256 + tid;
      int kr = idx >> 4, cg = idx & 15;
      int src = tap*16384 + (c0 + kr)*128 + cg*8;
      cpasync16(&Bh[kr*BP + cg*8], whi + src, true);
      cpasync16(&Bl[kr*BP + cg*8], wlo + src, true);
    }
  };

  fill(0, 0);
  CP_COMMIT();

  for (int it = 0; it < NIT; ++it){
    const int b = it & 1;
    if (it + 1 < NIT){
      fill(b ^ 1, it + 1);
      CP_COMMIT();
      CP_WAIT1();
    } else {
      CP_WAIT0();
    }
    __syncthreads();

    const unsigned short* Ah = dsm + b*STG;
    const unsigned short* Al = Ah + ASZ;
    const unsigned short* Bh = Ah + 2*ASZ;
    const unsigned short* Bl = Bh + BSZ;

    #pragma unroll
    for (int k16 = 0; k16 < 2; k16++){
      uint32_t af[4][4], bh[2][4], bl[2][4];
      #pragma unroll
      for (int mi = 0; mi < 4; mi++){
        int r = warp_m*64 + mi*16 + a_row_in;
        ldsm4(af[mi], &Ah[r*AP + k16*16 + a_colb]);
      }
      #pragma unroll
      for (int nj = 0; nj < 2; nj++){
        int kr = k16*16 + b_krow;
        int nc = warp_n*32 + nj*16 + b_coln;
        ldsm4t(bh[nj], &Bh[kr*BP + nc]);
        ldsm4t(bl[nj], &Bl[kr*BP + nc]);
      }
      #pragma unroll
      for (int mi = 0; mi < 4; mi++)
        #pragma unroll
        for (int ni = 0; ni < 4; ni++){
          const uint32_t* h = &bh[ni>>1][(ni&1)*2];
          const uint32_t* L = &bl[ni>>1][(ni&1)*2];
          mma_bf16(acc[mi][ni], af[mi], h[0], h[1]);
          mma_bf16(acc[mi][ni], af[mi], L[0], L[1]);
        }
      #pragma unroll
      for (int mi = 0; mi < 4; mi++){
        int r = warp_m*64 + mi*16 + a_row_in;
        ldsm4(af[mi], &Al[r*AP + k16*16 + a_colb]);
      }
      #pragma unroll
      for (int mi = 0; mi < 4; mi++)
        #pragma unroll
        for (int ni = 0; ni < 4; ni++){
          const uint32_t* h = &bh[ni>>1][(ni&1)*2];
          mma_bf16(acc[mi][ni], af[mi], h[0], h[1]);
        }
    }
    __syncthreads();
  }

  // epilogue (R9-proven): bias + relu, linear stores
  #pragma unroll
  for (int mi = 0; mi < 4; mi++){
    int v0 = vbase + warp_m*64 + mi*16 + (lane >> 2);
    #pragma unroll
    for (int ni = 0; ni < 4; ni++){
      int col = warp_n*32 + ni*8 + (lane & 3)*2;
      float2 bb = *(const float2*)&bias[col];
      float2 r0, r1;
      r0.x = fmaxf(acc[mi][ni][0] + bb.x, 0.f);
      r0.y = fmaxf(acc[mi][ni][1] + bb.y, 0.f);
      r1.x = fmaxf(acc[mi][ni][2] + bb.x, 0.f);
      r1.y = fmaxf(acc[mi][ni][3] + bb.y, 0.f);
      *(float2*)&out[(size_t)v0*128 + col]     = r0;
      *(float2*)&out[(size_t)(v0+8)*128 + col] = r1;
    }
  }
}

// ---------------------------------------------------------------------------
// R10-PROVEN (verbatim): L3 on HMMA, stride-2 parity decomposition.
// ---------------------------------------------------------------------------
__global__ __launch_bounds__(256, 2) void mma_s2(
    const __nv_bfloat16* __restrict__ xhi, const __nv_bfloat16* __restrict__ xlo,
    const __nv_bfloat16* __restrict__ whi, const __nv_bfloat16* __restrict__ wlo,
    const float* __restrict__ bias, float* __restrict__ out)
{
  constexpr int BM = 128, BK = 32;
  constexpr int AP = 40;
  constexpr int BP = 136;

  __shared__ __align__(16) unsigned short Ahi[BM*AP];
  __shared__ __align__(16) unsigned short Alo[BM*AP];
  __shared__ __align__(16) unsigned short Bhi[BK*BP];
  __shared__ __align__(16) unsigned short Blo[BK*BP];
  __shared__ int offs[BM];

  const int tid  = threadIdx.x;
  const int lane = tid & 31;
  const int wid  = tid >> 5;
  const int warp_m = wid >> 2;
  const int warp_n = wid & 3;
  const int vbase = blockIdx.x * BM;
  const int pz = blockIdx.z;
  const int pd = (pz >> 2) & 1, ph = (pz >> 1) & 1, pw = pz & 1;

  int md, mh, mw;
  { int rv = vbase + (tid & 127);
    mw = rv & 15; int t = rv >> 4; mh = t & 15; md = t >> 4; }

  int nkd, kdL[2], ddL[2];
  int nkh, khL[2], dhL[2];
  int nkw, kwL[2], dwL[2];
  auto mk2 = [&](int p, int& n, int* kL, int* dL){
    if (p == 0){ n = 2; kL[0]=0; kL[1]=2; dL[0]=-1; dL[1]=0; }
    else       { n = 1; kL[0]=1; dL[0]=0; }
  };
  mk2(pd, nkd, kdL, ddL);
  mk2(ph, nkh, khL, dhL);
  mk2(pw, nkw, kwL, dwL);

  const int a_row_in = lane & 15;
  const int a_colb   = (lane >> 4) << 3;
  const int b_krow   = lane & 15;
  const int b_coln   = (lane >> 4) << 3;

  float acc[4][4][4];
  #pragma unroll
  for (int mi = 0; mi < 4; mi++)
    #pragma unroll
    for (int ni = 0; ni < 4; ni++)
      #pragma unroll
      for (int q = 0; q < 4; q++) acc[mi][ni][q] = 0.f;

  for (int ia = 0; ia < nkd; ia++)
  for (int ib = 0; ib < nkh; ib++)
  for (int ic = 0; ic < nkw; ic++){
    const int tap = (kdL[ia]*3 + khL[ib])*3 + kwL[ic];
    __syncthreads();
    if (tid < BM){
      int id = md + ddL[ia], ih = mh + dhL[ib], iw = mw + dwL[ic];
      bool v = (unsigned)id < 16u && (unsigned)ih < 16u && (unsigned)iw < 16u;
      offs[tid] = v ? ((id*16 + ih)*16 + iw) * 128 : -1;
    }

    for (int c0 = 0; c0 < 128; c0 += BK){
      __syncthreads();
      #pragma unroll
      for (int rep = 0; rep < 2; rep++){
        int idx = rep * 256 + tid;
        int row = idx >> 2, cg = idx & 3;
        int o = offs[row];
        uint4 h = make_uint4(0,0,0,0), l = make_uint4(0,0,0,0);
        if (o >= 0){
          h = *(const uint4*)(xhi + o + c0 + cg*8);
          l = *(const uint4*)(xlo + o + c0 + cg*8);
        }
        *(uint4*)&Ahi[row*AP + cg*8] = h;
        *(uint4*)&Alo[row*AP + cg*8] = l;
      }
      #pragma unroll
      for (int rep = 0; rep < 2; rep++){
        int idx = rep * 256 + tid;
        int kr = idx >> 4, cg = idx & 15;
        int src = tap*16384 + (c0 + kr)*128 + cg*8;
        *(uint4*)&Bhi[kr*BP + cg*8] = *(const uint4*)(whi + src);
        *(uint4*)&Blo[kr*BP + cg*8] = *(const uint4*)(wlo + src);
      }
      __syncthreads();

      #pragma unroll
      for (int k16 = 0; k16 < 2; k16++){
        uint32_t af[4][4], bh[2][4], bl[2][4];
        #pragma unroll
        for (int mi = 0; mi < 4; mi++){
          int r = warp_m*64 + mi*16 + a_row_in;
          ldsm4(af[mi], &Ahi[r*AP + k16*16 + a_colb]);
        }
        #pragma unroll
        for (int nj = 0; nj < 2; nj++){
          int kr = k16*16 + b_krow;
          int nc = warp_n*32 + nj*16 + b_coln;
          ldsm4t(bh[nj], &Bhi[kr*BP + nc]);
          ldsm4t(bl[nj], &Blo[kr*BP + nc]);
        }
        #pragma unroll
        for (int mi = 0; mi < 4; mi++)
          #pragma unroll
          for (int ni = 0; ni < 4; ni++){
            const uint32_t* h = &bh[ni>>1][(ni&1)*2];
            const uint32_t* L = &bl[ni>>1][(ni&1)*2];
            mma_bf16(acc[mi][ni], af[mi], h[0], h[1]);
            mma_bf16(acc[mi][ni], af[mi], L[0], L[1]);
          }
        #pragma unroll
        for (int mi = 0; mi < 4; mi++){
          int r = warp_m*64 + mi*16 + a_row_in;
          ldsm4(af[mi], &Alo[r*AP + k16*16 + a_colb]);
        }
        #pragma unroll
        for (int mi = 0; mi < 4; mi++)
          #pragma unroll
          for (int ni = 0; ni < 4; ni++){
            const uint32_t* h = &bh[ni>>1][(ni&1)*2];
            mma_bf16(acc[mi][ni], af[mi], h[0], h[1]);
          }
      }
    }
  }

  #pragma unroll
  for (int mi = 0; mi < 4; mi++){
    int lv0 = warp_m*64 + mi*16 + (lane >> 2);
    #pragma unroll
    for (int ni = 0; ni < 4; ni++){
      int col = warp_n*32 + ni*8 + (lane & 3)*2;
      float2 bb = *(const float2*)&bias[col];
      #pragma unroll
      for (int h = 0; h < 2; h++){
        int rv = vbase + lv0 + h*8;
        int vw = rv & 15; int t = rv >> 4; int vh = t & 15; int vd = t >> 4;
        int od = 2*vd + pd, oh = 2*vh + ph, ow = 2*vw + pw;
        size_t oo = (size_t)((od*32 + oh)*32 + ow) * 128 + col;
        float2 r;
        r.x = acc[mi][ni][2*h+0] + bb.x;
        r.y = acc[mi][ni][2*h+1] + bb.y;
        *(float2*)&out[oo] = r;
      }
    }
  }
}

// ---------------------------------------------------------------------------
// Fused L5+L6 path tables (R6-proven).
// ---------------------------------------------------------------------------
__device__ __constant__ int c_np[2][3]   = {{2,2,0},{1,3,1}};
__device__ __constant__ int c_k1[2][3][3] = {{{1,0,0},{2,1,0},{0,0,0}},
                                             {{0,0,0},{2,1,0},{2,0,0}}};
__device__ __constant__ int c_k2[2][3][3] = {{{0,1,0},{1,2,0},{0,0,0}},
                                             {{0,0,0},{0,1,2},{2,0,0}}};

// P1 (R10-proven, verbatim): Wp + WpT
__global__ __launch_bounds__(256) void p1_wp(
    const float* __restrict__ w2, const float* __restrict__ w20)
{
  int t = blockIdx.x * 256 + threadIdx.x;
  if (t >= 27*27*128) return;
  int ci = t & 127;
  int k2l = (t >> 7) % 27;
  int k1l = t / (27*128);
  const float* a = w2 + ((size_t)k1l*128 + ci) * 64;
  const float* b = w20 + (size_t)k2l * 64 * 3;
  float s0 = 0.f, s1 = 0.f, s2 = 0.f;
  #pragma unroll 4
  for (int cm = 0; cm < 64; cm++){
    float av = a[cm];
    s0 = fmaf(av, b[cm*3+0], s0);
    s1 = fmaf(av, b[cm*3+1], s1);
    s2 = fmaf(av, b[cm*3+2], s2);
  }
  float* o = g_Wp + (size_t)t * 3;
  o[0] = s0; o[1] = s1; o[2] = s2;
  size_t kk = (size_t)k1l*27 + k2l;
  g_WpT[kk*384 + 0*128 + ci] = s0;
  g_WpT[kk*384 + 1*128 + ci] = s1;
  g_WpT[kk*384 + 2*128 + ci] = s2;
}

// P2 (R7-proven, verbatim): Weff[pz][dxl][co][ci]
__global__ __launch_bounds__(256) void p2_weff()
{
  int t = blockIdx.x * 256 + threadIdx.x;
  if (t >= 8*27*128) return;
  int ci = t & 127;
  int dxl = (t >> 7) % 27;
  int pz = t / (27*128);
  int jd = dxl / 9, jh = (dxl / 3) % 3, jw = dxl % 3;
  int pd = (pz >> 2) & 1, ph = (pz >> 1) & 1, pw = pz & 1;
  int nd = c_np[pd][jd], nh = c_np[ph][jh], nw = c_np[pw][jw];
  float s0 = 0.f, s1 = 0.f, s2 = 0.f;
  for (int a = 0; a < nd; a++)
  for (int b = 0; b < nh; b++)
  for (int c = 0; c < nw; c++){
    int k1l = (c_k1[pd][jd][a]*3 + c_k1[ph][jh][b])*3 + c_k1[pw][jw][c];
    int k2l = (c_k2[pd][jd][a]*3 + c_k2[ph][jh][b])*3 + c_k2[pw][jw][c];
    const float* wp = g_Wp + ((size_t)(k1l*27 + k2l)*128 + ci)*3;
    s0 += wp[0]; s1 += wp[1]; s2 += wp[2];
  }
  float* o = g_Weff + (size_t)(pz*27 + dxl) * 3 * 128;
  o[0*128 + ci] = s0;
  o[1*128 + ci] = s1;
  o[2*128 + ci] = s2;
}

// P3 (R6-proven, verbatim)
__global__ void p3_bias(const float* __restrict__ w20,
                        const float* __restrict__ b2,
                        const float* __restrict__ b20)
{
  int tid = threadIdx.x;
  if (tid < 81){
    int k2 = tid / 3, co = tid % 3;
    float s = 0.f;
    for (int cm = 0; cm < 64; cm++)
      s = fmaf(w20[(k2*64+cm)*3+co], b2[cm], s);
    g_bconv[tid] = s;
  }
  __syncthreads();
  if (tid < 3){
    float s = b20[tid];
    for (int k2 = 0; k2 < 27; k2++) s += g_bconv[k2*3+tid];
    g_btot[tid] = s;
  }
}

// ---------------------------------------------------------------------------
// Fused L5+L6 consumer (R7-proven, verbatim).
// ---------------------------------------------------------------------------
__global__ __launch_bounds__(256) void fused56b(
    const float* __restrict__ x, float* __restrict__ out)
{
  const int wid  = threadIdx.x >> 5;
  const int lane = threadIdx.x & 31;
  const int pz = blockIdx.z;
  const int pd = (pz >> 2) & 1, ph = (pz >> 1) & 1, pw = pz & 1;
  const int wg  = blockIdx.x * 8 + wid;
  const int seg = wg & 3;
  const int row = wg >> 2;
  const int rd = row >> 5, rh = row & 31;
  const int rw0 = seg * 8;
  const int l2 = 2 * lane;

  ull acc[8][3];
  #pragma unroll
  for (int r = 0; r < 8; r++)
    #pragma unroll
    for (int c = 0; c < 3; c++) acc[r][c] = 0ull;

  for (int jd = 0; jd <= 1 + pd; jd++){
    int id = rd + jd - 1;
    if ((unsigned)id >= 32u) continue;
    for (int jh = 0; jh <= 1 + ph; jh++){
      int ih = rh + jh - 1;
      if ((unsigned)ih >= 32u) continue;
      const float* xrow = x + (size_t)((id*32 + ih)*32) * 128;
      for (int jw = 0; jw <= 1 + pw; jw++){
        const int dxl = jd*9 + jh*3 + jw;
        const float* Wt = g_Weff + (size_t)(pz*27 + dxl) * 3 * 128;
        ull w00 = *(const ull*)(Wt +   0 + l2);
        ull w01 = *(const ull*)(Wt +  64 + l2);
        ull w10 = *(const ull*)(Wt + 128 + l2);
        ull w11 = *(const ull*)(Wt + 192 + l2);
        ull w20 = *(const ull*)(Wt + 256 + l2);
        ull w21 = *(const ull*)(Wt + 320 + l2);
        #pragma unroll
        for (int r = 0; r < 8; r++){
          int iw = rw0 + r + jw - 1;
          if ((unsigned)iw < 32u){
            const float* xp = xrow + iw * 128;
            ull x0 = *(const ull*)(xp + l2);
            ull x1 = *(const ull*)(xp + 64 + l2);
            ffma2(acc[r][0], x0, w00); ffma2(acc[r][0], x1, w01);
            ffma2(acc[r][1], x0, w10); ffma2(acc[r][1], x1, w11);
            ffma2(acc[r][2], x0, w20); ffma2(acc[r][2], x1, w21);
          }
        }
      }
    }
  }

  const float bt0 = g_btot[0], bt1 = g_btot[1], bt2 = g_btot[2];
  const int od = 2*rd + pd, oh = 2*rh + ph;

  #pragma unroll
  for (int r = 0; r < 8; r++){
    float s0, s1, s2;
    {
      float a, b;
      unpack2(acc[r][0], a, b); s0 = a + b;
      unpack2(acc[r][1], a, b); s1 = a + b;
      unpack2(acc[r][2], a, b); s2 = a + b;
    }
    #pragma unroll
    for (int sh = 16; sh > 0; sh >>= 1){
      s0 += __shfl_xor_sync(0xffffffffu, s0, sh);
      s1 += __shfl_xor_sync(0xffffffffu, s1, sh);
      s2 += __shfl_xor_sync(0xffffffffu, s2, sh);
    }
    if (lane == 0){
      int ow = 2*(rw0 + r) + pw;
      float* op = out + (size_t)((od*64 + oh)*64 + ow) * 3;
      op[0] = s0 + bt0;
      op[1] = s1 + bt1;
      op[2] = s2 + bt2;
    }
  }
}

// ---------------------------------------------------------------------------
// fix56w (R8-proven, verbatim): warp-per-voxel exact boundary fix.
// ---------------------------------------------------------------------------
__global__ __launch_bounds__(256) void fix56w(
    const float* __restrict__ x, const float* __restrict__ b20,
    float* __restrict__ out)
{
  const int gw = blockIdx.x * 8 + (threadIdx.x >> 5);
  const int lane = threadIdx.x & 31;
  const int l2 = 2 * lane;

  int plane = gw / 4096, r = gw % 4096;
  int a = r / 64, b = r % 64;
  int od, oh, ow;
  if      (plane == 0){ od = 0;  oh = a; ow = b; }
  else if (plane == 1){ od = 63; oh = a; ow = b; }
  else if (plane == 2){ oh = 0;  od = a; ow = b; if (od==0||od==63) return; }
  else if (plane == 3){ oh = 63; od = a; ow = b; if (od==0||od==63) return; }
  else if (plane == 4){ ow = 0;  od = a; oh = b; if (od==0||od==63||oh==0||oh==63) return; }
  else               { ow = 63; od = a; oh = b; if (od==0||od==63||oh==0||oh==63) return; }

  ull a0 = 0ull, a1 = 0ull, a2 = 0ull;
  float bias0 = __ldg(&b20[0]), bias1 = __ldg(&b20[1]), bias2 = __ldg(&b20[2]);

  for (int k2d = 0; k2d < 3; k2d++){
    int md = od + k2d - 1; if ((unsigned)md >= 64u) continue;
    int pmd = md & 1, rd = (md - pmd) >> 1;
    int n_d = pmd ? 1 : 2;
    int k1d[2], ixd[2];
    if (pmd){ k1d[0] = 1; ixd[0] = rd; }
    else    { k1d[0] = 0; ixd[0] = rd - 1; k1d[1] = 2; ixd[1] = rd; }
    for (int k2h = 0; k2h < 3; k2h++){
      int mh = oh + k2h - 1; if ((unsigned)mh >= 64u) continue;
      int pmh = mh & 1, rh = (mh - pmh) >> 1;
      int n_h = pmh ? 1 : 2;
      int k1h[2], ixh[2];
      if (pmh){ k1h[0] = 1; ixh[0] = rh; }
      else    { k1h[0] = 0; ixh[0] = rh - 1; k1h[1] = 2; ixh[1] = rh; }
      for (int k2w = 0; k2w < 3; k2w++){
        int mw = ow + k2w - 1; if ((unsigned)mw >= 64u) continue;
        int pmw = mw & 1, rw = (mw - pmw) >> 1;
        int n_w = pmw ? 1 : 2;
        int k1w[2], ixw[2];
        if (pmw){ k1w[0] = 1; ixw[0] = rw; }
        else    { k1w[0] = 0; ixw[0] = rw - 1; k1w[1] = 2; ixw[1] = rw; }

        int k2l = (k2d*3 + k2h)*3 + k2w;
        bias0 += g_bconv[k2l*3+0];
        bias1 += g_bconv[k2l*3+1];
        bias2 += g_bconv[k2l*3+2];

        for (int ia = 0; ia < n_d; ia++){
          if ((unsigned)ixd[ia] >= 32u) continue;
          for (int ib = 0; ib < n_h; ib++){
            if ((unsigned)ixh[ib] >= 32u) continue;
            for (int ic = 0; ic < n_w; ic++){
              if ((unsigned)ixw[ic] >= 32u) continue;
              int k1l = (k1d[ia]*3 + k1h[ib])*3 + k1w[ic];
              const float* wt = g_WpT + (size_t)(k1l*27 + k2l)*384;
              const float* xp = x + (size_t)((ixd[ia]*32 + ixh[ib])*32 + ixw[ic])*128;
              ull x0 = *(const ull*)(xp + l2);
              ull x1 = *(const ull*)(xp + 64 + l2);
              ffma2(a0, x0, *(const ull*)(wt +   0 + l2));
              ffma2(a0, x1, *(const ull*)(wt +  64 + l2));
              ffma2(a1, x0, *(const ull*)(wt + 128 + l2));
              ffma2(a1, x1, *(const ull*)(wt + 192 + l2));
              ffma2(a2, x0, *(const ull*)(wt + 256 + l2));
              ffma2(a2, x1, *(const ull*)(wt + 320 + l2));
            }
          }
        }
      }
    }
  }

  float s0, s1, s2;
  {
    float u, v;
    unpack2(a0, u, v); s0 = u + v;
    unpack2(a1, u, v); s1 = u + v;
    unpack2(a2, u, v); s2 = u + v;
  }
  #pragma unroll
  for (int sh = 16; sh > 0; sh >>= 1){
    s0 += __shfl_xor_sync(0xffffffffu, s0, sh);
    s1 += __shfl_xor_sync(0xffffffffu, s1, sh);
    s2 += __shfl_xor_sync(0xffffffffu, s2, sh);
  }
  if (lane == 0){
    float* op = out + (size_t)((od*64 + oh)*64 + ow) * 3;
    op[0] = s0 + bias0;
    op[1] = s1 + bias1;
    op[2] = s2 + bias2;
  }
}

// ---------------------------------------------------------------------------
// kernel_launch — launch #6 (ncu-profiled) = mma_s2.
// ---------------------------------------------------------------------------
extern "C" void kernel_launch(void* const* d_in, const int* in_sizes, int n_in,
                              void* d_out, int out_size)
{
  (void)in_sizes; (void)n_in; (void)out_size;
  const float* x   = (const float*)d_in[0];
  const float* w0  = (const float*)d_in[1];
  const float* b0  = (const float*)d_in[2];
  const float* w00 = (const float*)d_in[3];
  const float* b00 = (const float*)d_in[4];
  const float* w1  = (const float*)d_in[5];
  const float* b1  = (const float*)d_in[6];
  const float* w10 = (const float*)d_in[7];
  const float* b10 = (const float*)d_in[8];
  const float* w2  = (const float*)d_in[9];
  const float* b2  = (const float*)d_in[10];
  const float* w20 = (const float*)d_in[11];
  const float* b20 = (const float*)d_in[12];
  float* out = (float*)d_out;

  float *bufA = nullptr, *bufB = nullptr;
  __nv_bfloat16 *xhi, *xlo, *whi, *wlo, *whiB, *wloB;
  cudaGetSymbolAddress((void**)&bufA, g_bufA);
  cudaGetSymbolAddress((void**)&bufB, g_bufB);
  cudaGetSymbolAddress((void**)&xhi, g_xhi);
  cudaGetSymbolAddress((void**)&xlo, g_xlo);
  cudaGetSymbolAddress((void**)&whi, g_whi);
  cudaGetSymbolAddress((void**)&wlo, g_wlo);
  cudaGetSymbolAddress((void**)&whiB, g_whiB);
  cudaGetSymbolAddress((void**)&wloB, g_wloB);

  static bool attr_set = false;
  const int PIPE_SMEM = 2*37888 + 27*128*4;   // 89600 B
  if (!attr_set){
    cudaFuncSetAttribute(mma_s1r_pipe,
                         cudaFuncAttributeMaxDynamicSharedMemorySize, PIPE_SMEM);
    attr_set = true;
  }

  // (1) Wp + WpT precompute (input-only deps)
  p1_wp<<<(27*27*128 + 255)/256, 256>>>(w2, w20);
  // (2) split w1 for L3 HMMA
  split_w_kernel<<<1728, 256>>>(w1, whiB, wloB);
  // (3) L1: deconv0 s2: x(8^3,128) -> bufA(16^3,128)   [R1 proven]
  {
    dim3 g(512/32, 128/64, 8);
    deconv_gemm<32,2><<<g, 256>>>(x,  w0,  b0,  bufA,
                                  8,8,8,128,  16,16,16,128, 2, 0);
  }
  // (4) L2: deconv0_0 s1 + relu: bufA -> bufB(16^3,128)   [R1 proven]
  {
    dim3 g(4096/32, 128/64, 1);
    deconv_gemm<32,2><<<g, 256>>>(bufA, w00, b00, bufB,
                                  16,16,16,128, 16,16,16,128, 1, 1);
  }
  // (5) split L2 output for L3 HMMA
  split_x_kernel<<<512, 256>>>(bufB, xhi, xlo, 524288/4);
  // (6) L3 on HMMA   [R10 proven — profiled launch]
  {
    dim3 g(32, 1, 8);
    mma_s2<<<g, 256>>>(xhi, xlo, whiB, wloB, b1, bufA);
  }
  // (7) split w10 for L4 HMMA
  split_w_kernel<<<1728, 256>>>(w10, whi, wlo);
  // (8) split L3 output for L4 HMMA
  split_x_kernel<<<4096, 256>>>(bufA, xhi, xlo, 4194304/4);
  // (9) L4 on pipelined HMMA   [NEW]
  mma_s1r_pipe<<<256, 256, PIPE_SMEM>>>(xhi, xlo, whi, wlo, b10, bufB);
  // (10-11) fused-weight precompute for L5+L6
  p2_weff<<<(8*27*128 + 255)/256, 256>>>();
  p3_bias<<<1, 128>>>(w20, b2, b20);
  // (12) Fused L5+L6   [R7 proven]
  {
    dim3 g(512, 1, 8);
    fused56b<<<g, 256>>>(bufB, out);
  }
  // (13) Exact boundary fix   [R8 proven]
  fix56w<<<3072, 256>>>(bufB, b20, out);
}